// round 7
// baseline (speedup 1.0000x reference)
#include <cuda_runtime.h>
#include <cuda_bf16.h>
#include <math.h>

// Problem constants
constexpr int B_ = 8, N_ = 2048;
constexpr int M1 = 1024, M2 = 512;
constexpr int H1 = 128, C1OUT = 128;
constexpr int H2 = 256, C2OUT = 512;
constexpr int KMAX = 64;
constexpr int QPB = 16;   // queries per conv block
constexpr int MT  = 64;   // pair m-tile
constexpr int NT  = 128;  // n-tile
constexpr int KT  = 32;   // k-tile

// ---------------- scratch (__device__ globals; no allocation allowed) ----------------
// NOTE: referenced ONLY inside device code (host-side use passes host shadow!).
__device__ float g_p   [B_*N_*3];
__device__ int   g_idx1[B_*M1];
__device__ float g_pos1[B_*M1*3];
__device__ float g_P1  [B_*M1*H1];
__device__ float g_Q1  [B_*M1*H1];
__device__ float g_x1  [B_*M1*C1OUT];
__device__ int   g_idx2[B_*M2];
__device__ float g_pos2[B_*M2*3];
__device__ float g_P2  [B_*M2*H2];
__device__ float g_Q2  [B_*M2*H2];

// ---------------- normalize: per-cloud mean / unbiased std ----------------
__global__ void k_normalize(const float* __restrict__ pos) {
    int b = blockIdx.x, tid = threadIdx.x;           // 512 threads
    __shared__ float s_mean[3], s_den[3];
    const float* p = pos + b*N_*3;

    if (tid < 3) {
        float s = 0.f;
        for (int i = 0; i < N_; ++i) s = __fadd_rn(s, p[i*3 + tid]);
        s_mean[tid] = __fdiv_rn(s, (float)N_);
    }
    __syncthreads();
    if (tid < 3) {
        float mu = s_mean[tid];
        float s = 0.f;
        for (int i = 0; i < N_; ++i) {
            float d = __fsub_rn(p[i*3 + tid], mu);
            s = __fadd_rn(s, __fmul_rn(d, d));
        }
        float var = __fdiv_rn(s, (float)(N_ - 1));
        s_den[tid] = __fadd_rn(__fsqrt_rn(var), 1e-6f);
    }
    __syncthreads();
    float mx = s_mean[0], my = s_mean[1], mz = s_mean[2];
    float dx0 = s_den[0], dy0 = s_den[1], dz0 = s_den[2];
    for (int i = tid; i < N_; i += 512) {
        g_p[(b*N_+i)*3+0] = __fdiv_rn(__fsub_rn(p[i*3+0], mx), dx0);
        g_p[(b*N_+i)*3+1] = __fdiv_rn(__fsub_rn(p[i*3+1], my), dy0);
        g_p[(b*N_+i)*3+2] = __fdiv_rn(__fsub_rn(p[i*3+2], mz), dz0);
    }
}

// ---------------- farthest point sampling ----------------
// LVL==1: g_p[2048] -> g_idx1/g_pos1[1024];  LVL==2: g_pos1[1024] -> g_idx2/g_pos2[512]
template<int NP, int KSEL, int PT, int LVL>
__global__ void __launch_bounds__(NP/PT)
k_fps() {
    const float* src   = (LVL == 1) ? g_p    : g_pos1;
    int*       idx_out = (LVL == 1) ? g_idx1 : g_idx2;
    float*     pos_out = (LVL == 1) ? g_pos1 : g_pos2;

    constexpr int T = NP / PT;    // threads (1024)
    int b = blockIdx.x, t = threadIdx.x;
    int lane = t & 31, w = t >> 5;
    __shared__ float sx[NP], sy[NP], sz[NP];
    __shared__ unsigned wb[T/32];
    __shared__ int wi[T/32];
    __shared__ int s_win;
    const float* p = src + b*NP*3;

    float px[PT], py[PT], pz[PT], dd[PT];
    #pragma unroll
    for (int s=0;s<PT;s++){
        int i = t + s*T;
        float x=p[i*3+0], y=p[i*3+1], z=p[i*3+2];
        px[s]=x; py[s]=y; pz[s]=z; dd[s]=1e10f;
        sx[i]=x; sy[i]=y; sz[i]=z;
    }
    if (t==0){
        s_win = 0;
        idx_out[b*KSEL] = 0;
        pos_out[(b*KSEL)*3+0]=px[0]; pos_out[(b*KSEL)*3+1]=py[0]; pos_out[(b*KSEL)*3+2]=pz[0];
    }
    __syncthreads();

    for (int it=1; it<KSEL; ++it) {
        int last = s_win;
        float lx=sx[last], ly=sy[last], lz=sz[last];
        float bd = -1.f; int bi = 0;
        #pragma unroll
        for (int s=0;s<PT;s++){
            float dx=__fsub_rn(px[s],lx), dy=__fsub_rn(py[s],ly), dz=__fsub_rn(pz[s],lz);
            float d = __fadd_rn(__fadd_rn(__fmul_rn(dx,dx),__fmul_rn(dy,dy)),__fmul_rn(dz,dz));
            dd[s] = fminf(dd[s], d);
            if (dd[s] > bd) { bd = dd[s]; bi = t + s*T; }   // strict > : lower index wins ties
        }
        unsigned mybits = __float_as_uint(bd);              // dist >= 0 -> monotone bits
        unsigned mb = __reduce_max_sync(0xffffffffu, mybits);
        unsigned cand = (mybits == mb) ? (unsigned)bi : 0xffffffffu;
        unsigned mi = __reduce_min_sync(0xffffffffu, cand);
        if (lane==0){ wb[w]=mb; wi[w]=(int)mi; }
        __syncthreads();
        if (w==0){
            unsigned vb = wb[lane]; int vi = wi[lane];     // 32 warps
            unsigned mb2 = __reduce_max_sync(0xffffffffu, vb);
            unsigned cand2 = (vb==mb2) ? (unsigned)vi : 0xffffffffu;
            unsigned mi2 = __reduce_min_sync(0xffffffffu, cand2);
            if (lane==0){
                int win = (int)mi2;
                s_win = win;
                idx_out[b*KSEL+it] = win;
                pos_out[(b*KSEL+it)*3+0]=sx[win];
                pos_out[(b*KSEL+it)*3+1]=sy[win];
                pos_out[(b*KSEL+it)*3+2]=sz[win];
            }
        }
        __syncthreads();
    }
}

// ---------------- level-1 P/Q precompute (BN folded) ----------------
__global__ void k_prep1(const float* __restrict__ w1, const float* __restrict__ b1,
                        const float* __restrict__ g, const float* __restrict__ beta,
                        const float* __restrict__ m, const float* __restrict__ v) {
    int idx = blockIdx.x*256 + threadIdx.x;
    if (idx >= B_*M1*H1) return;
    int c = idx & (H1-1), pj = idx >> 7;
    float x = g_pos1[pj*3+0], y = g_pos1[pj*3+1], z = g_pos1[pj*3+2];
    float s = g[c] / sqrtf(v[c] + 1e-5f);
    float t = beta[c] - m[c]*s;
    float wa0=w1[0*H1+c], wa1=w1[1*H1+c], wa2=w1[2*H1+c];
    float wb0=w1[3*H1+c], wb1=w1[4*H1+c], wb2=w1[5*H1+c];
    float A = x*(wa0+wb0) + y*(wa1+wb1) + z*(wa2+wb2) + b1[c];
    g_P1[idx] = A * s;
    float q = -(x*wb0 + y*wb1 + z*wb2);
    g_Q1[idx] = q * s + t;
}

// ---------------- level-2 P precompute: gathered GEMM [4096,128]@[128,256] ----------------
__global__ void k_prep2(const float* __restrict__ w1, const float* __restrict__ b1,
                        const float* __restrict__ g, const float* __restrict__ v) {
    extern __shared__ char smemraw[];
    float* xs = (float*)smemraw;            // [64][128]
    float* ws = xs + 64*128;                // [128][68] padded
    int tid = threadIdx.x;                  // 256
    int row0 = blockIdx.x * 64;             // global row in [0,4096)
    int n0   = blockIdx.y * 64;
    int b = row0 / M2;

    for (int i = tid; i < 64*128; i += 256) {
        int r = i >> 7, k = i & 127;
        int jj = g_idx2[row0 + r];
        xs[r*128 + k] = g_x1[(b*M1 + jj)*H1 + k];
    }
    for (int i = tid; i < 128*64; i += 256) {
        int k = i >> 6, nn = i & 63;
        ws[k*68 + nn] = w1[k*H2 + n0 + nn];
    }
    __syncthreads();

    int ty = tid >> 4, tx = tid & 15;
    float acc[4][4] = {};
    #pragma unroll 4
    for (int k = 0; k < 128; ++k) {
        float a0 = xs[(ty*4+0)*128 + k];
        float a1 = xs[(ty*4+1)*128 + k];
        float a2 = xs[(ty*4+2)*128 + k];
        float a3 = xs[(ty*4+3)*128 + k];
        float4 bv = *(const float4*)&ws[k*68 + tx*4];
        acc[0][0]+=a0*bv.x; acc[0][1]+=a0*bv.y; acc[0][2]+=a0*bv.z; acc[0][3]+=a0*bv.w;
        acc[1][0]+=a1*bv.x; acc[1][1]+=a1*bv.y; acc[1][2]+=a1*bv.z; acc[1][3]+=a1*bv.w;
        acc[2][0]+=a2*bv.x; acc[2][1]+=a2*bv.y; acc[2][2]+=a2*bv.z; acc[2][3]+=a2*bv.w;
        acc[3][0]+=a3*bv.x; acc[3][1]+=a3*bv.y; acc[3][2]+=a3*bv.z; acc[3][3]+=a3*bv.w;
    }
    #pragma unroll
    for (int mi=0; mi<4; ++mi) {
        int r = row0 + ty*4 + mi;
        float px = g_pos2[r*3+0], py = g_pos2[r*3+1], pz = g_pos2[r*3+2];
        #pragma unroll
        for (int ni=0; ni<4; ++ni) {
            int n = n0 + tx*4 + ni;
            float s = g[n] / sqrtf(v[n] + 1e-5f);
            float A = acc[mi][ni]
                    + px*w1[128*H2 + n] + py*w1[129*H2 + n] + pz*w1[130*H2 + n] + b1[n];
            g_P2[r*H2 + n] = A * s;
        }
    }
}

__global__ void k_prep2q(const float* __restrict__ w1, const float* __restrict__ g,
                         const float* __restrict__ beta, const float* __restrict__ m,
                         const float* __restrict__ v) {
    int idx = blockIdx.x*256 + threadIdx.x;
    if (idx >= B_*M2*H2) return;
    int c = idx & (H2-1), pj = idx >> 8;
    float x = g_pos2[pj*3+0], y = g_pos2[pj*3+1], z = g_pos2[pj*3+2];
    float s = g[c] / sqrtf(v[c] + 1e-5f);
    float t = beta[c] - m[c]*s;
    float q = -(x*w1[128*H2+c] + y*w1[129*H2+c] + z*w1[130*H2+c]);
    g_Q2[idx] = q * s + t;
}

// ---------------- ball-query + pair-list GEMM + max aggregation ----------------
constexpr size_t conv_smem_bytes(int MSRC, int HDIM, int COUT) {
    return (size_t)(MSRC*3 + QPB*KMAX + QPB*KMAX + QPB + QPB*KMAX + QPB*KMAX + 32
                    + MT*HDIM + KT*(NT+4) + QPB*COUT) * 4;
}

template<int MSRC, int HDIM, int COUT, int LVL>
__global__ void __launch_bounds__(512)
k_conv(const float* __restrict__ w2, const float* __restrict__ b2,
       float* __restrict__ out_ext, float R2) {
    const float* srcpos = (LVL == 1) ? g_pos1 : g_pos2;
    const float* P      = (LVL == 1) ? g_P1   : g_P2;
    const float* Q      = (LVL == 1) ? g_Q1   : g_Q2;
    float*       out    = (LVL == 1) ? g_x1   : out_ext;

    extern __shared__ char smemraw[];
    float*    s_pos = (float*)smemraw;                 // MSRC*3
    float*    s_pd  = s_pos + MSRC*3;                  // QPB*KMAX
    int*      s_pj  = (int*)(s_pd + QPB*KMAX);         // QPB*KMAX
    int*      s_cnt = s_pj + QPB*KMAX;                 // QPB
    int*      s_fi  = s_cnt + QPB;                     // QPB*KMAX
    int*      s_fj  = s_fi + QPB*KMAX;                 // QPB*KMAX
    int*      s_qoff= s_fj + QPB*KMAX;                 // 32
    float*    s_h   = (float*)(s_qoff + 32);           // MT*HDIM
    float*    s_w   = s_h + MT*HDIM;                   // KT*(NT+4)
    unsigned* s_out = (unsigned*)(s_w + KT*(NT+4));    // QPB*COUT

    int blk = blockIdx.x;
    int b  = blk / (MSRC/QPB);
    int q0 = (blk % (MSRC/QPB)) * QPB;
    int tid = threadIdx.x, lane = tid & 31, w = tid >> 5;

    for (int i = tid; i < MSRC*3; i += 512) s_pos[i] = srcpos[b*MSRC*3 + i];
    __syncthreads();

    // ---- pair build: warp w handles query q0+w ----
    {
        int qi = q0 + w;
        float qx = s_pos[qi*3+0], qy = s_pos[qi*3+1], qz = s_pos[qi*3+2];
        int cnt = 0;
        for (int base = 0; base < MSRC; base += 32) {
            int j = base + lane;
            float dx = __fsub_rn(s_pos[j*3+0], qx);
            float dy = __fsub_rn(s_pos[j*3+1], qy);
            float dz = __fsub_rn(s_pos[j*3+2], qz);
            float d2 = __fadd_rn(__fadd_rn(__fmul_rn(dx,dx),__fmul_rn(dy,dy)),__fmul_rn(dz,dz));
            bool pred = (d2 <= R2);
            unsigned ball = __ballot_sync(0xffffffffu, pred);
            int nb = __popc(ball);
            if (cnt + nb <= KMAX) {
                if (pred) {
                    int pos = cnt + __popc(ball & ((1u<<lane)-1u));
                    s_pj[w*KMAX+pos] = j; s_pd[w*KMAX+pos] = d2;
                }
                cnt += nb;
            } else {
                // rare slow path: keep K smallest d2 (ties -> lower j kept)
                unsigned rem = ball;
                while (rem) {
                    int l = __ffs(rem)-1; rem &= rem-1u;
                    float cd2 = __shfl_sync(0xffffffffu, d2, l);
                    int cj = base + l;
                    if (cnt < KMAX) {
                        if (lane==0){ s_pj[w*KMAX+cnt]=cj; s_pd[w*KMAX+cnt]=cd2; }
                        cnt++;
                    } else {
                        float e0 = s_pd[w*KMAX+lane],    e1 = s_pd[w*KMAX+32+lane];
                        int   j0 = s_pj[w*KMAX+lane],    j1 = s_pj[w*KMAX+32+lane];
                        float md; int ms, mj;
                        if (e1 > e0 || (e1==e0 && j1>j0)) { md=e1; ms=32+lane; mj=j1; }
                        else                               { md=e0; ms=lane;    mj=j0; }
                        #pragma unroll
                        for (int o=16;o;o>>=1){
                            float od = __shfl_xor_sync(~0u, md, o);
                            int   os = __shfl_xor_sync(~0u, ms, o);
                            int   oj = __shfl_xor_sync(~0u, mj, o);
                            if (od > md || (od==md && oj>mj)) { md=od; ms=os; mj=oj; }
                        }
                        if (cd2 < md) {
                            if (lane==0){ s_pj[w*KMAX+ms]=cj; s_pd[w*KMAX+ms]=cd2; }
                        }
                    }
                    __syncwarp();
                }
            }
        }
        if (lane==0) s_cnt[w] = cnt;
    }
    __syncthreads();

    if (tid==0){
        int acc=0;
        for (int i=0;i<QPB;i++){ s_qoff[i]=acc; acc+=s_cnt[i]; }
        s_qoff[QPB]=acc;
    }
    __syncthreads();
    {
        int off = s_qoff[w], c = s_cnt[w];
        for (int e = lane; e < c; e += 32){ s_fi[off+e]=w; s_fj[off+e]=s_pj[w*KMAX+e]; }
    }
    for (int i = tid; i < QPB*COUT; i += 512) s_out[i] = 0u;
    __syncthreads();

    int total = s_qoff[QPB];
    int ty = tid >> 5, tx = tid & 31;

    for (int m0 = 0; m0 < total; m0 += MT) {
        // hidden tile: h = relu(P_j + Q_i)
        for (int i = tid; i < MT*HDIM; i += 512) {
            int mp = i / HDIM, k = i % HDIM;
            float val = 0.f;
            if (m0 + mp < total) {
                int qi = s_fi[m0+mp], j = s_fj[m0+mp];
                val = fmaxf(P[(size_t)(b*MSRC + j)*HDIM + k] + Q[(size_t)(b*MSRC + q0 + qi)*HDIM + k], 0.f);
            }
            s_h[i] = val;
        }
        __syncthreads();

        for (int n0 = 0; n0 < COUT; n0 += NT) {
            float acc[4][4] = {};
            for (int k0 = 0; k0 < HDIM; k0 += KT) {
                for (int i = tid; i < KT*NT; i += 512) {
                    int kk = i / NT, nn = i % NT;
                    s_w[kk*(NT+4)+nn] = w2[(size_t)(k0+kk)*COUT + n0 + nn];
                }
                __syncthreads();
                #pragma unroll
                for (int kk = 0; kk < KT; ++kk) {
                    float a0 = s_h[(ty*4+0)*HDIM + k0+kk];
                    float a1 = s_h[(ty*4+1)*HDIM + k0+kk];
                    float a2 = s_h[(ty*4+2)*HDIM + k0+kk];
                    float a3 = s_h[(ty*4+3)*HDIM + k0+kk];
                    float4 bv = *(const float4*)&s_w[kk*(NT+4) + tx*4];
                    acc[0][0]+=a0*bv.x; acc[0][1]+=a0*bv.y; acc[0][2]+=a0*bv.z; acc[0][3]+=a0*bv.w;
                    acc[1][0]+=a1*bv.x; acc[1][1]+=a1*bv.y; acc[1][2]+=a1*bv.z; acc[1][3]+=a1*bv.w;
                    acc[2][0]+=a2*bv.x; acc[2][1]+=a2*bv.y; acc[2][2]+=a2*bv.z; acc[2][3]+=a2*bv.w;
                    acc[3][0]+=a3*bv.x; acc[3][1]+=a3*bv.y; acc[3][2]+=a3*bv.z; acc[3][3]+=a3*bv.w;
                }
                __syncthreads();
            }
            #pragma unroll
            for (int mi=0; mi<4; ++mi) {
                int mp = ty*4 + mi;
                if (m0 + mp < total) {
                    int qi = s_fi[m0+mp];
                    #pragma unroll
                    for (int ni=0; ni<4; ++ni) {
                        int n = n0 + tx*4 + ni;
                        float val = fmaxf(acc[mi][ni] + b2[n], 0.f);
                        atomicMax(&s_out[qi*COUT + n], __float_as_uint(val));
                    }
                }
            }
            __syncthreads();
        }
    }

    for (int i = tid; i < QPB*COUT; i += 512) {
        int q = i / COUT, c = i % COUT;
        out[(size_t)(b*MSRC + q0 + q)*COUT + c] = __uint_as_float(s_out[i]);
    }
}

// batch2: write as FLOAT — the output buffer is a single float32 array
// (ints 0..7 written as raw int32 read back as float denormals -> rel_err 1.0).
__global__ void k_batch2(float* __restrict__ out) {
    int i = blockIdx.x*256 + threadIdx.x;
    if (i < B_*M2) out[i] = (float)(i >> 9);   // batch id 0..7
}

// ---------------- launch ----------------
extern "C" void kernel_launch(void* const* d_in, const int* in_sizes, int n_in,
                              void* d_out, int out_size) {
    const float *pos, *c1_w1, *c1_b1, *c1_g, *c1_be, *c1_m, *c1_v, *c1_w2, *c1_b2;
    const float *c2_w1, *c2_b1, *c2_g, *c2_be, *c2_m, *c2_v, *c2_w2, *c2_b2;
    if (in_sizes[0] == B_*N_*3) {
        // setup_inputs insertion order
        pos   = (const float*)d_in[0];
        c1_w1 = (const float*)d_in[1];  c1_b1 = (const float*)d_in[2];
        c1_g  = (const float*)d_in[3];  c1_be = (const float*)d_in[4];
        c1_m  = (const float*)d_in[5];  c1_v  = (const float*)d_in[6];
        c1_w2 = (const float*)d_in[7];  c1_b2 = (const float*)d_in[8];
        c2_w1 = (const float*)d_in[9];  c2_b1 = (const float*)d_in[10];
        c2_g  = (const float*)d_in[11]; c2_be = (const float*)d_in[12];
        c2_m  = (const float*)d_in[13]; c2_v  = (const float*)d_in[14];
        c2_w2 = (const float*)d_in[15]; c2_b2 = (const float*)d_in[16];
    } else {
        // alphabetical fallback
        c1_b1 = (const float*)d_in[1];  c1_b2 = (const float*)d_in[2];
        c1_be = (const float*)d_in[3];  c1_g  = (const float*)d_in[4];
        c1_m  = (const float*)d_in[5];  c1_v  = (const float*)d_in[6];
        c1_w1 = (const float*)d_in[7];  c1_w2 = (const float*)d_in[8];
        c2_b1 = (const float*)d_in[9];  c2_b2 = (const float*)d_in[10];
        c2_be = (const float*)d_in[11]; c2_g  = (const float*)d_in[12];
        c2_m  = (const float*)d_in[13]; c2_v  = (const float*)d_in[14];
        c2_w1 = (const float*)d_in[15]; c2_w2 = (const float*)d_in[16];
        pos   = (const float*)d_in[17];
    }
    float* out = (float*)d_out;

    const size_t smem1 = conv_smem_bytes(M1, H1, C1OUT);
    const size_t smem2 = conv_smem_bytes(M2, H2, C2OUT);
    const size_t smemP2 = (64*128 + 128*68) * sizeof(float);
    cudaFuncSetAttribute(k_conv<M1,H1,C1OUT,1>, cudaFuncAttributeMaxDynamicSharedMemorySize, (int)smem1);
    cudaFuncSetAttribute(k_conv<M2,H2,C2OUT,2>, cudaFuncAttributeMaxDynamicSharedMemorySize, (int)smem2);
    cudaFuncSetAttribute(k_prep2, cudaFuncAttributeMaxDynamicSharedMemorySize, (int)smemP2);

    k_normalize<<<B_, 512>>>(pos);
    k_fps<N_, M1, 2, 1><<<B_, 1024>>>();
    k_prep1<<<(B_*M1*H1 + 255)/256, 256>>>(c1_w1, c1_b1, c1_g, c1_be, c1_m, c1_v);
    {
        float r2 = (float)(0.1 * 0.1);   // matches JAX f32 scalar exactly
        k_conv<M1,H1,C1OUT,1><<<B_*(M1/QPB), 512, smem1>>>(c1_w2, c1_b2, nullptr, r2);
    }
    k_fps<M1, M2, 1, 2><<<B_, 1024>>>();
    k_prep2<<<dim3(B_*M2/64, H2/64), 256, smemP2>>>(c2_w1, c2_b1, c2_g, c2_v);
    k_prep2q<<<(B_*M2*H2 + 255)/256, 256>>>(c2_w1, c2_g, c2_be, c2_m, c2_v);
    {
        float r2 = (float)(0.25 * 0.25);
        k_conv<M2,H2,C2OUT,2><<<B_*(M2/QPB), 512, smem2>>>(c2_w2, c2_b2, out, r2);
    }
    if ((size_t)out_size >= (size_t)B_*M2*C2OUT + B_*M2) {
        k_batch2<<<(B_*M2 + 255)/256, 256>>>(out + (size_t)B_*M2*C2OUT);
    }
    (void)in_sizes; (void)n_in;
}

// round 8
// speedup vs baseline: 1.6131x; 1.6131x over previous
#include <cuda_runtime.h>
#include <cuda_bf16.h>
#include <math.h>

// Problem constants
constexpr int B_ = 8, N_ = 2048;
constexpr int M1 = 1024, M2 = 512;
constexpr int H1 = 128, C1OUT = 128;
constexpr int H2 = 256, C2OUT = 512;
constexpr int KMAX = 64;
constexpr int QPB = 32;   // queries per conv block (2 per warp)
constexpr int MT  = 64;   // pair m-tile
constexpr int NT  = 128;  // n-tile
constexpr int KT  = 32;   // k-tile

// ---------------- scratch (__device__ globals; no allocation allowed) ----------------
// NOTE: referenced ONLY inside device code (host-side use passes host shadow!).
__device__ float g_p   [B_*N_*3];
__device__ int   g_idx1[B_*M1];
__device__ float g_pos1[B_*M1*3];
__device__ float g_P1  [B_*M1*H1];
__device__ float g_Q1  [B_*M1*H1];
__device__ float g_x1  [B_*M1*C1OUT];
__device__ int   g_idx2[B_*M2];
__device__ float g_pos2[B_*M2*3];
__device__ float g_P2  [B_*M2*H2];
__device__ float g_Q2  [B_*M2*H2];

// ---------------- normalize: per-cloud mean / unbiased std ----------------
// Sequential per-coordinate accumulation (bit-matches reference; verified pass).
__global__ void k_normalize(const float* __restrict__ pos) {
    int b = blockIdx.x, tid = threadIdx.x;           // 512 threads
    __shared__ float s_mean[3], s_den[3];
    const float* p = pos + b*N_*3;

    if (tid < 3) {
        float s = 0.f;
        for (int i = 0; i < N_; ++i) s = __fadd_rn(s, p[i*3 + tid]);
        s_mean[tid] = __fdiv_rn(s, (float)N_);
    }
    __syncthreads();
    if (tid < 3) {
        float mu = s_mean[tid];
        float s = 0.f;
        for (int i = 0; i < N_; ++i) {
            float d = __fsub_rn(p[i*3 + tid], mu);
            s = __fadd_rn(s, __fmul_rn(d, d));
        }
        float var = __fdiv_rn(s, (float)(N_ - 1));
        s_den[tid] = __fadd_rn(__fsqrt_rn(var), 1e-6f);
    }
    __syncthreads();
    float mx = s_mean[0], my = s_mean[1], mz = s_mean[2];
    float dx0 = s_den[0], dy0 = s_den[1], dz0 = s_den[2];
    for (int i = tid; i < N_; i += 512) {
        g_p[(b*N_+i)*3+0] = __fdiv_rn(__fsub_rn(p[i*3+0], mx), dx0);
        g_p[(b*N_+i)*3+1] = __fdiv_rn(__fsub_rn(p[i*3+1], my), dy0);
        g_p[(b*N_+i)*3+2] = __fdiv_rn(__fsub_rn(p[i*3+2], mz), dz0);
    }
}

// ---------------- farthest point sampling (single-barrier, double-buffered) ----------------
// LVL==1: g_p[2048] -> g_idx1/g_pos1[1024];  LVL==2: g_pos1[1024] -> g_idx2/g_pos2[512]
template<int NP, int KSEL, int PT, int LVL>
__global__ void __launch_bounds__(512)
k_fps() {
    constexpr int T  = NP / PT;   // 512 threads
    constexpr int NW = T / 32;    // 16 warps
    const float* src   = (LVL == 1) ? g_p    : g_pos1;
    int*       idx_out = (LVL == 1) ? g_idx1 : g_idx2;
    float*     pos_out = (LVL == 1) ? g_pos1 : g_pos2;

    int b = blockIdx.x, t = threadIdx.x;
    int lane = t & 31, w = t >> 5;
    __shared__ float sx[NP], sy[NP], sz[NP];
    __shared__ unsigned wb[2][32];
    __shared__ int wi[2][32];
    __shared__ int s_hist[KSEL];
    const float* p = src + b*NP*3;

    float px[PT], py[PT], pz[PT], dd[PT];
    #pragma unroll
    for (int s=0;s<PT;s++){
        int i = t + s*T;
        float x=p[i*3+0], y=p[i*3+1], z=p[i*3+2];
        px[s]=x; py[s]=y; pz[s]=z; dd[s]=1e10f;
        sx[i]=x; sy[i]=y; sz[i]=z;
    }
    if (t < 32) { wb[0][t]=0u; wb[1][t]=0u; wi[0][t]=0x7fffffff; wi[1][t]=0x7fffffff; }
    if (t==0) s_hist[0] = 0;
    __syncthreads();

    int win = 0;                      // every thread tracks the winner locally
    for (int it=1; it<KSEL; ++it) {
        float lx=sx[win], ly=sy[win], lz=sz[win];   // broadcast LDS
        float bd = -1.f; int bi = 0;
        #pragma unroll
        for (int s=0;s<PT;s++){
            float dx=__fsub_rn(px[s],lx), dy=__fsub_rn(py[s],ly), dz=__fsub_rn(pz[s],lz);
            float d = __fadd_rn(__fadd_rn(__fmul_rn(dx,dx),__fmul_rn(dy,dy)),__fmul_rn(dz,dz));
            dd[s] = fminf(dd[s], d);
            if (dd[s] > bd) { bd = dd[s]; bi = t + s*T; }  // strict > : lowest index per thread
        }
        unsigned mybits = __float_as_uint(bd);             // dist >= 0 -> monotone bits
        unsigned mb = __reduce_max_sync(0xffffffffu, mybits);
        unsigned cand = (mybits == mb) ? (unsigned)bi : 0xffffffffu;
        unsigned mi = __reduce_min_sync(0xffffffffu, cand);
        int par = it & 1;                                   // parity double-buffer
        if (lane==0){ wb[par][w]=mb; wi[par][w]=(int)mi; }
        __syncthreads();                                    // ONLY barrier per iteration
        // redundant 2nd stage in every warp -> winner in registers, no 2nd barrier
        unsigned vb = (lane < NW) ? wb[par][lane] : 0u;
        int      vi = (lane < NW) ? wi[par][lane] : 0x7fffffff;
        unsigned mb2 = __reduce_max_sync(0xffffffffu, vb);
        unsigned cand2 = (vb==mb2) ? (unsigned)vi : 0xffffffffu;
        win = (int)__reduce_min_sync(0xffffffffu, cand2);
        if (t==0) s_hist[it] = win;
    }
    __syncthreads();
    // bulk write-out (off the serial critical path)
    for (int i = t; i < KSEL; i += T) {
        int h = s_hist[i];
        idx_out[b*KSEL+i] = h;
        pos_out[(b*KSEL+i)*3+0] = sx[h];
        pos_out[(b*KSEL+i)*3+1] = sy[h];
        pos_out[(b*KSEL+i)*3+2] = sz[h];
    }
}

// ---------------- level-1 P/Q precompute (BN folded) ----------------
__global__ void k_prep1(const float* __restrict__ w1, const float* __restrict__ b1,
                        const float* __restrict__ g, const float* __restrict__ beta,
                        const float* __restrict__ m, const float* __restrict__ v) {
    int idx = blockIdx.x*256 + threadIdx.x;
    if (idx >= B_*M1*H1) return;
    int c = idx & (H1-1), pj = idx >> 7;
    float x = g_pos1[pj*3+0], y = g_pos1[pj*3+1], z = g_pos1[pj*3+2];
    float s = g[c] / sqrtf(v[c] + 1e-5f);
    float t = beta[c] - m[c]*s;
    float wa0=w1[0*H1+c], wa1=w1[1*H1+c], wa2=w1[2*H1+c];
    float wb0=w1[3*H1+c], wb1=w1[4*H1+c], wb2=w1[5*H1+c];
    float A = x*(wa0+wb0) + y*(wa1+wb1) + z*(wa2+wb2) + b1[c];
    g_P1[idx] = A * s;
    float q = -(x*wb0 + y*wb1 + z*wb2);
    g_Q1[idx] = q * s + t;
}

// ---------------- level-2 P precompute: gathered GEMM [4096,128]@[128,256] ----------------
__global__ void k_prep2(const float* __restrict__ w1, const float* __restrict__ b1,
                        const float* __restrict__ g, const float* __restrict__ v) {
    extern __shared__ char smemraw[];
    float* xs = (float*)smemraw;            // [64][128]
    float* ws = xs + 64*128;                // [128][68] padded
    int tid = threadIdx.x;                  // 256
    int row0 = blockIdx.x * 64;             // global row in [0,4096)
    int n0   = blockIdx.y * 64;
    int b = row0 / M2;

    for (int i = tid; i < 64*128; i += 256) {
        int r = i >> 7, k = i & 127;
        int jj = g_idx2[row0 + r];
        xs[r*128 + k] = g_x1[(b*M1 + jj)*H1 + k];
    }
    for (int i = tid; i < 128*64; i += 256) {
        int k = i >> 6, nn = i & 63;
        ws[k*68 + nn] = w1[k*H2 + n0 + nn];
    }
    __syncthreads();

    int ty = tid >> 4, tx = tid & 15;
    float acc[4][4] = {};
    #pragma unroll 4
    for (int k = 0; k < 128; ++k) {
        float a0 = xs[(ty*4+0)*128 + k];
        float a1 = xs[(ty*4+1)*128 + k];
        float a2 = xs[(ty*4+2)*128 + k];
        float a3 = xs[(ty*4+3)*128 + k];
        float4 bv = *(const float4*)&ws[k*68 + tx*4];
        acc[0][0]+=a0*bv.x; acc[0][1]+=a0*bv.y; acc[0][2]+=a0*bv.z; acc[0][3]+=a0*bv.w;
        acc[1][0]+=a1*bv.x; acc[1][1]+=a1*bv.y; acc[1][2]+=a1*bv.z; acc[1][3]+=a1*bv.w;
        acc[2][0]+=a2*bv.x; acc[2][1]+=a2*bv.y; acc[2][2]+=a2*bv.z; acc[2][3]+=a2*bv.w;
        acc[3][0]+=a3*bv.x; acc[3][1]+=a3*bv.y; acc[3][2]+=a3*bv.z; acc[3][3]+=a3*bv.w;
    }
    #pragma unroll
    for (int mi=0; mi<4; ++mi) {
        int r = row0 + ty*4 + mi;
        float px = g_pos2[r*3+0], py = g_pos2[r*3+1], pz = g_pos2[r*3+2];
        #pragma unroll
        for (int ni=0; ni<4; ++ni) {
            int n = n0 + tx*4 + ni;
            float s = g[n] / sqrtf(v[n] + 1e-5f);
            float A = acc[mi][ni]
                    + px*w1[128*H2 + n] + py*w1[129*H2 + n] + pz*w1[130*H2 + n] + b1[n];
            g_P2[r*H2 + n] = A * s;
        }
    }
}

__global__ void k_prep2q(const float* __restrict__ w1, const float* __restrict__ g,
                         const float* __restrict__ beta, const float* __restrict__ m,
                         const float* __restrict__ v) {
    int idx = blockIdx.x*256 + threadIdx.x;
    if (idx >= B_*M2*H2) return;
    int c = idx & (H2-1), pj = idx >> 8;
    float x = g_pos2[pj*3+0], y = g_pos2[pj*3+1], z = g_pos2[pj*3+2];
    float s = g[c] / sqrtf(v[c] + 1e-5f);
    float t = beta[c] - m[c]*s;
    float q = -(x*w1[128*H2+c] + y*w1[129*H2+c] + z*w1[130*H2+c]);
    g_Q2[idx] = q * s + t;
}

// ---------------- ball-query + pair-list GEMM + max aggregation ----------------
constexpr size_t conv_smem_bytes(int MSRC, int HDIM, int COUT) {
    return (size_t)(MSRC*3 + QPB*KMAX + QPB*KMAX + QPB + QPB*KMAX + QPB*KMAX + 64
                    + MT*HDIM + KT*(NT+4) + QPB*COUT) * 4;
}

template<int MSRC, int HDIM, int COUT, int LVL>
__global__ void __launch_bounds__(512)
k_conv(const float* __restrict__ w2, const float* __restrict__ b2,
       float* __restrict__ out_ext, float R2) {
    const float* srcpos = (LVL == 1) ? g_pos1 : g_pos2;
    const float* P      = (LVL == 1) ? g_P1   : g_P2;
    const float* Q      = (LVL == 1) ? g_Q1   : g_Q2;
    float*       out    = (LVL == 1) ? g_x1   : out_ext;

    extern __shared__ char smemraw[];
    float*    s_pos = (float*)smemraw;                 // MSRC*3
    float*    s_pd  = s_pos + MSRC*3;                  // QPB*KMAX
    int*      s_pj  = (int*)(s_pd + QPB*KMAX);         // QPB*KMAX
    int*      s_cnt = s_pj + QPB*KMAX;                 // QPB
    int*      s_fi  = s_cnt + QPB;                     // QPB*KMAX
    int*      s_fj  = s_fi + QPB*KMAX;                 // QPB*KMAX
    int*      s_qoff= s_fj + QPB*KMAX;                 // 64
    float*    s_h   = (float*)(s_qoff + 64);           // MT*HDIM
    float*    s_w   = s_h + MT*HDIM;                   // KT*(NT+4)
    unsigned* s_out = (unsigned*)(s_w + KT*(NT+4));    // QPB*COUT

    int blk = blockIdx.x;
    int b  = blk / (MSRC/QPB);
    int q0 = (blk % (MSRC/QPB)) * QPB;
    int tid = threadIdx.x, lane = tid & 31, w = tid >> 5;

    for (int i = tid; i < MSRC*3; i += 512) s_pos[i] = srcpos[b*MSRC*3 + i];
    __syncthreads();

    // ---- pair build: warp w handles queries q0+2w, q0+2w+1 ----
    for (int qq = 0; qq < 2; ++qq) {
        int qslot = w*2 + qq;
        int qi = q0 + qslot;
        float qx = s_pos[qi*3+0], qy = s_pos[qi*3+1], qz = s_pos[qi*3+2];
        int cnt = 0;
        for (int base = 0; base < MSRC; base += 32) {
            int j = base + lane;
            float dx = __fsub_rn(s_pos[j*3+0], qx);
            float dy = __fsub_rn(s_pos[j*3+1], qy);
            float dz = __fsub_rn(s_pos[j*3+2], qz);
            float d2 = __fadd_rn(__fadd_rn(__fmul_rn(dx,dx),__fmul_rn(dy,dy)),__fmul_rn(dz,dz));
            bool pred = (d2 <= R2);
            unsigned ball = __ballot_sync(0xffffffffu, pred);
            int nb = __popc(ball);
            if (cnt + nb <= KMAX) {
                if (pred) {
                    int pos = cnt + __popc(ball & ((1u<<lane)-1u));
                    s_pj[qslot*KMAX+pos] = j; s_pd[qslot*KMAX+pos] = d2;
                }
                cnt += nb;
            } else {
                // rare slow path: keep K smallest d2 (ties -> lower j kept)
                unsigned rem = ball;
                while (rem) {
                    int l = __ffs(rem)-1; rem &= rem-1u;
                    float cd2 = __shfl_sync(0xffffffffu, d2, l);
                    int cj = base + l;
                    if (cnt < KMAX) {
                        if (lane==0){ s_pj[qslot*KMAX+cnt]=cj; s_pd[qslot*KMAX+cnt]=cd2; }
                        cnt++;
                    } else {
                        float e0 = s_pd[qslot*KMAX+lane],    e1 = s_pd[qslot*KMAX+32+lane];
                        int   j0 = s_pj[qslot*KMAX+lane],    j1 = s_pj[qslot*KMAX+32+lane];
                        float md; int ms, mj;
                        if (e1 > e0 || (e1==e0 && j1>j0)) { md=e1; ms=32+lane; mj=j1; }
                        else                               { md=e0; ms=lane;    mj=j0; }
                        #pragma unroll
                        for (int o=16;o;o>>=1){
                            float od = __shfl_xor_sync(~0u, md, o);
                            int   os = __shfl_xor_sync(~0u, ms, o);
                            int   oj = __shfl_xor_sync(~0u, mj, o);
                            if (od > md || (od==md && oj>mj)) { md=od; ms=os; mj=oj; }
                        }
                        if (cd2 < md) {
                            if (lane==0){ s_pj[qslot*KMAX+ms]=cj; s_pd[qslot*KMAX+ms]=cd2; }
                        }
                    }
                    __syncwarp();
                }
            }
        }
        if (lane==0) s_cnt[qslot] = cnt;
    }
    __syncthreads();

    if (tid==0){
        int acc=0;
        for (int i=0;i<QPB;i++){ s_qoff[i]=acc; acc+=s_cnt[i]; }
        s_qoff[QPB]=acc;
    }
    __syncthreads();
    for (int qq = 0; qq < 2; ++qq) {
        int qslot = w*2 + qq;
        int off = s_qoff[qslot], c = s_cnt[qslot];
        for (int e = lane; e < c; e += 32){ s_fi[off+e]=qslot; s_fj[off+e]=s_pj[qslot*KMAX+e]; }
    }
    for (int i = tid; i < QPB*COUT; i += 512) s_out[i] = 0u;
    __syncthreads();

    int total = s_qoff[QPB];
    int ty = tid >> 5, tx = tid & 31;

    for (int m0 = 0; m0 < total; m0 += MT) {
        // hidden tile: h = relu(P_j + Q_i)
        for (int i = tid; i < MT*HDIM; i += 512) {
            int mp = i / HDIM, k = i % HDIM;
            float val = 0.f;
            if (m0 + mp < total) {
                int qi = s_fi[m0+mp], j = s_fj[m0+mp];
                val = fmaxf(P[(size_t)(b*MSRC + j)*HDIM + k] + Q[(size_t)(b*MSRC + q0 + qi)*HDIM + k], 0.f);
            }
            s_h[i] = val;
        }
        __syncthreads();

        for (int n0 = 0; n0 < COUT; n0 += NT) {
            float acc[4][4] = {};
            for (int k0 = 0; k0 < HDIM; k0 += KT) {
                for (int i = tid; i < KT*NT; i += 512) {
                    int kk = i / NT, nn = i % NT;
                    s_w[kk*(NT+4)+nn] = w2[(size_t)(k0+kk)*COUT + n0 + nn];
                }
                __syncthreads();
                #pragma unroll
                for (int kk = 0; kk < KT; ++kk) {
                    float a0 = s_h[(ty*4+0)*HDIM + k0+kk];
                    float a1 = s_h[(ty*4+1)*HDIM + k0+kk];
                    float a2 = s_h[(ty*4+2)*HDIM + k0+kk];
                    float a3 = s_h[(ty*4+3)*HDIM + k0+kk];
                    float4 bv = *(const float4*)&s_w[kk*(NT+4) + tx*4];
                    acc[0][0]+=a0*bv.x; acc[0][1]+=a0*bv.y; acc[0][2]+=a0*bv.z; acc[0][3]+=a0*bv.w;
                    acc[1][0]+=a1*bv.x; acc[1][1]+=a1*bv.y; acc[1][2]+=a1*bv.z; acc[1][3]+=a1*bv.w;
                    acc[2][0]+=a2*bv.x; acc[2][1]+=a2*bv.y; acc[2][2]+=a2*bv.z; acc[2][3]+=a2*bv.w;
                    acc[3][0]+=a3*bv.x; acc[3][1]+=a3*bv.y; acc[3][2]+=a3*bv.z; acc[3][3]+=a3*bv.w;
                }
                __syncthreads();
            }
            #pragma unroll
            for (int mi=0; mi<4; ++mi) {
                int mp = ty*4 + mi;
                if (m0 + mp < total) {
                    int qi = s_fi[m0+mp];
                    #pragma unroll
                    for (int ni=0; ni<4; ++ni) {
                        int n = n0 + tx*4 + ni;
                        float val = fmaxf(acc[mi][ni] + b2[n], 0.f);
                        atomicMax(&s_out[qi*COUT + n], __float_as_uint(val));
                    }
                }
            }
            __syncthreads();
        }
    }

    for (int i = tid; i < QPB*COUT; i += 512) {
        int q = i / COUT, c = i % COUT;
        out[(size_t)(b*MSRC + q0 + q)*COUT + c] = __uint_as_float(s_out[i]);
    }
}

// batch2: second output written as float32 into the shared float output buffer.
__global__ void k_batch2(float* __restrict__ out) {
    int i = blockIdx.x*256 + threadIdx.x;
    if (i < B_*M2) out[i] = (float)(i >> 9);   // batch id 0..7
}

// ---------------- launch ----------------
extern "C" void kernel_launch(void* const* d_in, const int* in_sizes, int n_in,
                              void* d_out, int out_size) {
    const float *pos, *c1_w1, *c1_b1, *c1_g, *c1_be, *c1_m, *c1_v, *c1_w2, *c1_b2;
    const float *c2_w1, *c2_b1, *c2_g, *c2_be, *c2_m, *c2_v, *c2_w2, *c2_b2;
    if (in_sizes[0] == B_*N_*3) {
        // setup_inputs insertion order
        pos   = (const float*)d_in[0];
        c1_w1 = (const float*)d_in[1];  c1_b1 = (const float*)d_in[2];
        c1_g  = (const float*)d_in[3];  c1_be = (const float*)d_in[4];
        c1_m  = (const float*)d_in[5];  c1_v  = (const float*)d_in[6];
        c1_w2 = (const float*)d_in[7];  c1_b2 = (const float*)d_in[8];
        c2_w1 = (const float*)d_in[9];  c2_b1 = (const float*)d_in[10];
        c2_g  = (const float*)d_in[11]; c2_be = (const float*)d_in[12];
        c2_m  = (const float*)d_in[13]; c2_v  = (const float*)d_in[14];
        c2_w2 = (const float*)d_in[15]; c2_b2 = (const float*)d_in[16];
    } else {
        // alphabetical fallback
        c1_b1 = (const float*)d_in[1];  c1_b2 = (const float*)d_in[2];
        c1_be = (const float*)d_in[3];  c1_g  = (const float*)d_in[4];
        c1_m  = (const float*)d_in[5];  c1_v  = (const float*)d_in[6];
        c1_w1 = (const float*)d_in[7];  c1_w2 = (const float*)d_in[8];
        c2_b1 = (const float*)d_in[9];  c2_b2 = (const float*)d_in[10];
        c2_be = (const float*)d_in[11]; c2_g  = (const float*)d_in[12];
        c2_m  = (const float*)d_in[13]; c2_v  = (const float*)d_in[14];
        c2_w1 = (const float*)d_in[15]; c2_w2 = (const float*)d_in[16];
        pos   = (const float*)d_in[17];
    }
    float* out = (float*)d_out;

    const size_t smem1 = conv_smem_bytes(M1, H1, C1OUT);
    const size_t smem2 = conv_smem_bytes(M2, H2, C2OUT);
    const size_t smemP2 = (64*128 + 128*68) * sizeof(float);
    cudaFuncSetAttribute(k_conv<M1,H1,C1OUT,1>, cudaFuncAttributeMaxDynamicSharedMemorySize, (int)smem1);
    cudaFuncSetAttribute(k_conv<M2,H2,C2OUT,2>, cudaFuncAttributeMaxDynamicSharedMemorySize, (int)smem2);
    cudaFuncSetAttribute(k_prep2, cudaFuncAttributeMaxDynamicSharedMemorySize, (int)smemP2);

    k_normalize<<<B_, 512>>>(pos);
    k_fps<N_, M1, 4, 1><<<B_, 512>>>();
    k_prep1<<<(B_*M1*H1 + 255)/256, 256>>>(c1_w1, c1_b1, c1_g, c1_be, c1_m, c1_v);
    {
        float r2 = (float)(0.1 * 0.1);   // matches JAX f32 scalar exactly
        k_conv<M1,H1,C1OUT,1><<<B_*(M1/QPB), 512, smem1>>>(c1_w2, c1_b2, nullptr, r2);
    }
    k_fps<M1, M2, 2, 2><<<B_, 512>>>();
    k_prep2<<<dim3(B_*M2/64, H2/64), 256, smemP2>>>(c2_w1, c2_b1, c2_g, c2_v);
    k_prep2q<<<(B_*M2*H2 + 255)/256, 256>>>(c2_w1, c2_g, c2_be, c2_m, c2_v);
    {
        float r2 = (float)(0.25 * 0.25);
        k_conv<M2,H2,C2OUT,2><<<B_*(M2/QPB), 512, smem2>>>(c2_w2, c2_b2, out, r2);
    }
    if ((size_t)out_size >= (size_t)B_*M2*C2OUT + B_*M2) {
        k_batch2<<<(B_*M2 + 255)/256, 256>>>(out + (size_t)B_*M2*C2OUT);
    }
    (void)in_sizes; (void)n_in;
}